// round 5
// baseline (speedup 1.0000x reference)
#include <cuda_runtime.h>

// Scratch: split-K partials [16][512*256] (8 MB) and x3 [512 x 64].
static __device__ float g_part[16][512 * 256];
static __device__ float g_x3[512 * 64];

// ---------------------------------------------------------------------------
// Kernel A1: split-K partial GEMM.  part[z] = x[64r x 32k] @ w2^T[32k x 64h]
// grid (8, 4, 16) = 512 blocks, 256 threads, 4x4 register tiles,
// 16-strided rows/cols (conflict-free LDS.128), 4 blocks/SM forced.
// ---------------------------------------------------------------------------
__global__ void __launch_bounds__(256, 4) gemm1_part_kernel(
    const float* __restrict__ x,    // [512, 512]
    const float* __restrict__ w2)   // [256, 512]
{
    __shared__ float xs[64][36];
    __shared__ float ws[64][36];

    const int t  = threadIdx.x;
    const int r0 = blockIdx.x * 64;
    const int h0 = blockIdx.y * 64;
    const int k0 = blockIdx.z * 32;

    #pragma unroll
    for (int i = 0; i < 2; ++i) {
        const int idx = t + i * 256;
        const int r   = idx >> 3;
        const int kq  = (idx & 7) * 4;
        float4 vx = *reinterpret_cast<const float4*>(
            x + (size_t)(r0 + r) * 512 + k0 + kq);
        *reinterpret_cast<float4*>(&xs[r][kq]) = vx;
        float4 vw = *reinterpret_cast<const float4*>(
            w2 + (size_t)(h0 + r) * 512 + k0 + kq);
        *reinterpret_cast<float4*>(&ws[r][kq]) = vw;
    }

    float acc[4][4];
    #pragma unroll
    for (int i = 0; i < 4; ++i)
        #pragma unroll
        for (int j = 0; j < 4; ++j) acc[i][j] = 0.f;

    const int tx = t & 15;
    const int ty = t >> 4;

    __syncthreads();

    #pragma unroll
    for (int kq = 0; kq < 32; kq += 4) {
        float4 a[4];
        #pragma unroll
        for (int i = 0; i < 4; ++i)
            a[i] = *reinterpret_cast<const float4*>(&xs[ty + 16 * i][kq]);
        #pragma unroll
        for (int j = 0; j < 4; ++j) {
            const float4 bv = *reinterpret_cast<const float4*>(&ws[tx + 16 * j][kq]);
            #pragma unroll
            for (int i = 0; i < 4; ++i) {
                acc[i][j] = fmaf(a[i].x, bv.x, acc[i][j]);
                acc[i][j] = fmaf(a[i].y, bv.y, acc[i][j]);
                acc[i][j] = fmaf(a[i].z, bv.z, acc[i][j]);
                acc[i][j] = fmaf(a[i].w, bv.w, acc[i][j]);
            }
        }
    }

    float* dst = g_part[blockIdx.z];
    #pragma unroll
    for (int i = 0; i < 4; ++i)
        #pragma unroll
        for (int j = 0; j < 4; ++j)
            dst[(size_t)(r0 + ty + 16 * i) * 256 + h0 + tx + 16 * j] = acc[i][j];
}

// ---------------------------------------------------------------------------
// Kernel A2: reduce 16 partials + bias + LeakyReLU, GEMM2 + softmaxes -> x3.
// ---------------------------------------------------------------------------
__global__ void __launch_bounds__(256) head_kernel(
    const float* __restrict__ b2,   // [256]
    const float* __restrict__ w3,   // [55, 256]
    const float* __restrict__ b3)   // [55]
{
    __shared__ float hs[4][256];
    __shared__ float zs[4][60];

    const int t  = threadIdx.x;
    const int r0 = blockIdx.x * 4;

    const float bb = b2[t];
    #pragma unroll
    for (int i = 0; i < 4; ++i) {
        const size_t off = (size_t)(r0 + i) * 256 + t;
        float s = bb;
        #pragma unroll
        for (int z = 0; z < 16; ++z) s += g_part[z][off];
        hs[i][t] = (s >= 0.f) ? s : 0.01f * s;
    }
    __syncthreads();

    if (t < 220) {
        const int r = t / 55;
        const int c = t - 55 * r;
        const float4* hv = reinterpret_cast<const float4*>(hs[r]);
        const float4* wv = reinterpret_cast<const float4*>(w3 + (size_t)c * 256);
        float acc = 0.f;
        #pragma unroll 8
        for (int k = 0; k < 64; ++k) {
            const float4 a = hv[k];
            const float4 w = __ldg(&wv[k]);
            acc = fmaf(a.x, w.x, acc); acc = fmaf(a.y, w.y, acc);
            acc = fmaf(a.z, w.z, acc); acc = fmaf(a.w, w.w, acc);
        }
        zs[r][c] = acc + b3[c];
    }
    __syncthreads();

    if (t < 24) {
        const int r     = t / 6;
        const int g     = t - 6 * r;
        const int start = (g == 0) ? 0 : 5 + 10 * (g - 1);
        const int len   = (g == 0) ? 5 : 10;
        float m = -3.0e38f;
        for (int c = 0; c < len; ++c) m = fmaxf(m, zs[r][start + c]);
        float s = 0.f;
        for (int c = 0; c < len; ++c) s += __expf(zs[r][start + c] - m);
        const float inv = 1.0f / s;
        float* dst = &g_x3[(size_t)(r0 + r) * 64];
        for (int c = 0; c < len; ++c)
            dst[start + c] = __expf(zs[r][start + c] - m) * inv;
    }
}

// ---------------------------------------------------------------------------
// Kernel B: expansion.  out[b, i] constant over runs of 10 (r = i/10).
//
// grid (8, 512), 640 threads. Block bx covers floats [pad + 12800*bx, ...)
// = runs [1280*bx, 1280*bx + 1282). 12800 is a multiple of 2560 (one store
// iteration: 640 thr x 4 floats) and of 10, so rbase % 10 == 0 and every
// thread's run-phase is loop-invariant across the 5 store iterations.
//
// Run values hierarchically: v(r) = v(r/10) * (p[l+1]/p[l]) * p[5+10l + r%10]
// for r >= 10 (l = magnitude level). 130 parents get the full chain; the
// 1282 sv values are then 2 LDS + 2 FMUL each.
// ---------------------------------------------------------------------------
__global__ void __launch_bounds__(640) expand_kernel(float* __restrict__ out)
{
    __shared__ float p[64];
    __shared__ float rs[4];       // level scale: rs[l] = p[l+1]/p[l], l=1..3
    __shared__ float ps[132];     // parent run values v(128*bx + j)
    __shared__ float sv[1288];    // run values for this block

    const unsigned t   = threadIdx.x;
    const unsigned bx  = blockIdx.x;
    const unsigned b   = blockIdx.y;
    const unsigned pad = b & 3u;
    const unsigned rbase = bx * 1280u;   // multiple of 10

    if (t < 64u) p[t] = g_x3[(size_t)b * 64u + t];
    __syncthreads();

    // --- parents: full-chain run values for q = 128*bx + j, j in [0,130) ---
    if (t < 130u) {
        const unsigned q = bx * 128u + t;
        float v = 0.f;
        if (q == 0u) {
            v = p[0];
        } else if (q < 10u) {
            v = p[1] * p[5 + q];
        } else if (q < 100u) {
            const unsigned q1 = q / 10u;
            v = p[2] * p[5 + q1] * p[15 + (q - 10u * q1)];
        } else if (q < 1000u) {
            const unsigned q1 = q / 10u, q2 = q / 100u;
            v = p[3] * p[5 + q2] * p[15 + (q1 - 10u * q2)]
                     * p[25 + (q - 10u * q1)];
        } else {
            const unsigned q1 = q / 10u, q2 = q / 100u, q3 = q / 1000u;
            v = p[4] * p[5 + q3] * p[15 + (q2 - 10u * q3)]
                     * p[25 + (q1 - 10u * q2)] * p[35 + (q - 10u * q1)];
        }
        ps[t] = v;
    } else if (t >= 130u && t < 133u) {
        const unsigned l = t - 129u;          // 1..3
        rs[l] = p[l + 1] / p[l];
    }
    __syncthreads();

    // --- sv fill: runs [rbase, rbase + 1282) via parents ---
    #pragma unroll
    for (unsigned kk = 0; kk < 3u; ++kk) {
        const unsigned ri = t + kk * 640u;
        if (ri < 1282u) {
            const unsigned r = rbase + ri;
            float v = 0.f;
            if (r < 10000u) {
                if (r == 0u) {
                    v = p[0];
                } else if (r < 10u) {
                    v = p[1] * p[5 + r];
                } else {
                    const unsigned l  = 1u + (r >= 100u) + (r >= 1000u);
                    const unsigned rq = ri / 10u;
                    const unsigned d  = ri - 10u * rq;   // == r % 10
                    v = ps[rq] * rs[l] * p[5u + 10u * l + d];
                }
            }
            sv[ri] = v;
        }
    }
    __syncthreads();

    float* o = out + (size_t)b * 99999u;
    float4* ov = reinterpret_cast<float4*>(o + pad);   // 16B-aligned

    // loop-invariant per-thread phase
    const unsigned ph  = pad + 4u * t;       // < 2560
    const unsigned rt  = ph / 10u;
    const unsigned rem = ph - 10u * rt;
    const bool c1 = (rem + 1u < 10u);
    const bool c2 = (rem + 2u < 10u);
    const bool c3 = (rem + 3u < 10u);

    if (bx < 7u) {
        unsigned vi = bx * 3200u + t;
        unsigned ri = rt;
        #pragma unroll
        for (int k = 0; k < 5; ++k) {
            const float f0 = sv[ri];
            const float f1 = sv[ri + 1u];
            float4 w;
            w.x = f0;
            w.y = c1 ? f0 : f1;
            w.z = c2 ? f0 : f1;
            w.w = c3 ? f0 : f1;
            ov[vi] = w;
            vi += 640u;
            ri += 256u;
        }
        // head scalars + patch out[b, 0] (after this thread's stores)
        if (bx == 0u) {
            if (t == 0u) o[0] = p[1] * p[5];
            else if (t < pad) o[t] = p[0];   // pad <= 3
        }
    } else {
        // bx == 7: float4 indices [22400, 24999), guarded
        unsigned vi = 22400u + t;
        unsigned ri = rt;
        #pragma unroll
        for (int k = 0; k < 5; ++k) {
            if (vi < 24999u) {
                const float f0 = sv[ri];
                const float f1 = sv[ri + 1u];
                float4 w;
                w.x = f0;
                w.y = c1 ? f0 : f1;
                w.z = c2 ? f0 : f1;
                w.w = c3 ? f0 : f1;
                ov[vi] = w;
            }
            vi += 640u;
            ri += 256u;
        }
        // scalar tail: i in [pad + 99996, 99999), all run 9999 = rbase + 1039
        if (t < 3u - pad) {
            o[pad + 99996u + t] = sv[1039];
        }
    }
}

// ---------------------------------------------------------------------------
extern "C" void kernel_launch(void* const* d_in, const int* in_sizes, int n_in,
                              void* d_out, int out_size)
{
    (void)in_sizes; (void)n_in; (void)out_size;
    const float* x  = (const float*)d_in[0];   // [512, 512]
    const float* w2 = (const float*)d_in[1];   // [256, 512]
    const float* b2 = (const float*)d_in[2];   // [256]
    const float* w3 = (const float*)d_in[3];   // [55, 256]
    const float* b3 = (const float*)d_in[4];   // [55]
    float* out = (float*)d_out;                // [512, 99999]

    gemm1_part_kernel<<<dim3(8, 4, 16), 256>>>(x, w2);
    head_kernel<<<128, 256>>>(b2, w3, b3);
    expand_kernel<<<dim3(8, 512), 640>>>(out);
}

// round 6
// speedup vs baseline: 1.1139x; 1.1139x over previous
#include <cuda_runtime.h>

// Scratch: split-K partials [16][512*256] (8 MB) and x3 [512 x 64].
static __device__ float g_part[16][512 * 256];
static __device__ float g_x3[512 * 64];

// ---------------------------------------------------------------------------
// Kernel A1: split-K partial GEMM.  part[z] = x[64r x 32k] @ w2^T[32k x 64h]
// grid (8, 4, 16) = 512 blocks, 256 threads, 4x4 register tiles,
// 16-strided rows/cols (conflict-free LDS.128).  [R4 form — best measured]
// ---------------------------------------------------------------------------
__global__ void __launch_bounds__(256) gemm1_part_kernel(
    const float* __restrict__ x,    // [512, 512]
    const float* __restrict__ w2)   // [256, 512]
{
    __shared__ float xs[64][36];
    __shared__ float ws[64][36];

    const int t  = threadIdx.x;
    const int r0 = blockIdx.x * 64;
    const int h0 = blockIdx.y * 64;
    const int k0 = blockIdx.z * 32;

    #pragma unroll
    for (int i = 0; i < 2; ++i) {
        const int idx = t + i * 256;
        const int r   = idx >> 3;
        const int kq  = (idx & 7) * 4;
        float4 vx = *reinterpret_cast<const float4*>(
            x + (size_t)(r0 + r) * 512 + k0 + kq);
        *reinterpret_cast<float4*>(&xs[r][kq]) = vx;
        float4 vw = *reinterpret_cast<const float4*>(
            w2 + (size_t)(h0 + r) * 512 + k0 + kq);
        *reinterpret_cast<float4*>(&ws[r][kq]) = vw;
    }

    float acc[4][4];
    #pragma unroll
    for (int i = 0; i < 4; ++i)
        #pragma unroll
        for (int j = 0; j < 4; ++j) acc[i][j] = 0.f;

    const int tx = t & 15;
    const int ty = t >> 4;

    __syncthreads();

    #pragma unroll
    for (int kq = 0; kq < 32; kq += 4) {
        float4 a[4], bv[4];
        #pragma unroll
        for (int i = 0; i < 4; ++i)
            a[i] = *reinterpret_cast<const float4*>(&xs[ty + 16 * i][kq]);
        #pragma unroll
        for (int j = 0; j < 4; ++j)
            bv[j] = *reinterpret_cast<const float4*>(&ws[tx + 16 * j][kq]);
        #pragma unroll
        for (int i = 0; i < 4; ++i)
            #pragma unroll
            for (int j = 0; j < 4; ++j) {
                acc[i][j] = fmaf(a[i].x, bv[j].x, acc[i][j]);
                acc[i][j] = fmaf(a[i].y, bv[j].y, acc[i][j]);
                acc[i][j] = fmaf(a[i].z, bv[j].z, acc[i][j]);
                acc[i][j] = fmaf(a[i].w, bv[j].w, acc[i][j]);
            }
    }

    float* dst = g_part[blockIdx.z];
    #pragma unroll
    for (int i = 0; i < 4; ++i)
        #pragma unroll
        for (int j = 0; j < 4; ++j)
            dst[(size_t)(r0 + ty + 16 * i) * 256 + h0 + tx + 16 * j] = acc[i][j];
}

// ---------------------------------------------------------------------------
// Kernel A2 v2: reduce 16 partials + bias + LeakyReLU, then GEMM2 with w3
// staged through smem (coalesced), + softmaxes -> x3.
// One block per 8 batch rows, 256 threads, grid 64.
// Output mapping o -> (r = o & 7, c = o >> 3), o in [0, 440).
// ---------------------------------------------------------------------------
__global__ void __launch_bounds__(256) head_kernel(
    const float* __restrict__ b2,   // [256]
    const float* __restrict__ w3,   // [55, 256]
    const float* __restrict__ b3)   // [55]
{
    __shared__ float hs[8][260];    // 8 rows of h (stride 260: 16B-aligned, odd /16B)
    __shared__ float ws[55][68];    // w3 column-chunk (64 cols + pad)
    __shared__ float zs[8][60];

    const int t  = threadIdx.x;
    const int r0 = blockIdx.x * 8;

    // --- reduce partials + bias + LeakyReLU ---
    const float bb = b2[t];
    #pragma unroll
    for (int i = 0; i < 8; ++i) {
        const size_t off = (size_t)(r0 + i) * 256 + t;
        float s = bb;
        #pragma unroll
        for (int z = 0; z < 16; ++z) s += g_part[z][off];
        hs[i][t] = (s >= 0.f) ? s : 0.01f * s;
    }

    // --- GEMM2 with w3 chunked through smem ---
    const int o0 = t;                    // first owned output
    const int o1 = t + 256;              // second owned output (if < 440)
    const int r0o = o0 & 7, c0o = o0 >> 3;
    const int r1o = o1 & 7, c1o = o1 >> 3;
    float acc0 = 0.f, acc1 = 0.f;

    #pragma unroll
    for (int chunk = 0; chunk < 4; ++chunk) {
        __syncthreads();
        // load w3[:, chunk*64 : chunk*64+64] -> ws (880 float4, coalesced per row)
        for (int idx = t; idx < 880; idx += 256) {
            const int c = idx >> 4;          // 0..54
            const int j = (idx & 15) * 4;    // 0..60
            float4 v = *reinterpret_cast<const float4*>(
                w3 + (size_t)c * 256 + chunk * 64 + j);
            *reinterpret_cast<float4*>(&ws[c][j]) = v;
        }
        __syncthreads();

        #pragma unroll 4
        for (int k = 0; k < 16; ++k) {
            const int kj = k * 4;
            {
                const float4 a = *reinterpret_cast<const float4*>(
                    &hs[r0o][chunk * 64 + kj]);
                const float4 w = *reinterpret_cast<const float4*>(&ws[c0o][kj]);
                acc0 = fmaf(a.x, w.x, acc0); acc0 = fmaf(a.y, w.y, acc0);
                acc0 = fmaf(a.z, w.z, acc0); acc0 = fmaf(a.w, w.w, acc0);
            }
            if (o1 < 440) {
                const float4 a = *reinterpret_cast<const float4*>(
                    &hs[r1o][chunk * 64 + kj]);
                const float4 w = *reinterpret_cast<const float4*>(&ws[c1o][kj]);
                acc1 = fmaf(a.x, w.x, acc1); acc1 = fmaf(a.y, w.y, acc1);
                acc1 = fmaf(a.z, w.z, acc1); acc1 = fmaf(a.w, w.w, acc1);
            }
        }
    }
    zs[r0o][c0o] = acc0 + b3[c0o];
    if (o1 < 440) zs[r1o][c1o] = acc1 + b3[c1o];
    __syncthreads();

    // --- softmaxes: 8 rows x 6 groups ---
    if (t < 48) {
        const int r     = t / 6;
        const int g     = t - 6 * r;
        const int start = (g == 0) ? 0 : 5 + 10 * (g - 1);
        const int len   = (g == 0) ? 5 : 10;
        float m = -3.0e38f;
        for (int c = 0; c < len; ++c) m = fmaxf(m, zs[r][start + c]);
        float s = 0.f;
        for (int c = 0; c < len; ++c) s += __expf(zs[r][start + c] - m);
        const float inv = 1.0f / s;
        float* dst = &g_x3[(size_t)(r0 + r) * 64];
        for (int c = 0; c < len; ++c)
            dst[start + c] = __expf(zs[r][start + c] - m) * inv;
    }
}

// ---------------------------------------------------------------------------
// Kernel B: expansion.  out[b, i] constant over runs of 10 (r = i/10).
// grid (8, 512), 640 threads; loop-invariant per-thread run phase;
// streaming (evict-first) float4 stores.
// ---------------------------------------------------------------------------
__global__ void __launch_bounds__(640) expand_kernel(float* __restrict__ out)
{
    __shared__ float p[64];
    __shared__ float sv[1288];

    const unsigned t   = threadIdx.x;
    const unsigned bx  = blockIdx.x;
    const unsigned b   = blockIdx.y;
    const unsigned pad = b & 3u;
    const unsigned rbase = bx * 1280u;   // multiple of 10

    if (t < 64u) p[t] = g_x3[(size_t)b * 64u + t];
    __syncthreads();

    // --- run values for runs [rbase, rbase + 1282) ---
    #pragma unroll
    for (unsigned kk = 0; kk < 3u; ++kk) {
        const unsigned ri = t + kk * 640u;
        if (ri < 1282u) {
            const unsigned r = rbase + ri;
            float v = 0.f;
            if (r < 10000u) {
                if (r == 0u) {
                    v = p[0];
                } else if (r < 10u) {
                    v = p[1] * p[5 + r];
                } else if (r < 100u) {
                    const unsigned q1 = r / 10u;
                    v = p[2] * p[5 + q1] * p[15 + (r - 10u * q1)];
                } else if (r < 1000u) {
                    const unsigned q1 = r / 10u, q2 = r / 100u;
                    v = p[3] * p[5 + q2] * p[15 + (q1 - 10u * q2)]
                             * p[25 + (r - 10u * q1)];
                } else {
                    const unsigned q1 = r / 10u, q2 = r / 100u, q3 = r / 1000u;
                    v = p[4] * p[5 + q3] * p[15 + (q2 - 10u * q3)]
                             * p[25 + (q1 - 10u * q2)] * p[35 + (r - 10u * q1)];
                }
            }
            sv[ri] = v;
        }
    }
    __syncthreads();

    float* o = out + (size_t)b * 99999u;
    float4* ov = reinterpret_cast<float4*>(o + pad);   // 16B-aligned

    const unsigned ph  = pad + 4u * t;       // < 2560
    const unsigned rt  = ph / 10u;
    const unsigned rem = ph - 10u * rt;
    const bool c1 = (rem + 1u < 10u);
    const bool c2 = (rem + 2u < 10u);
    const bool c3 = (rem + 3u < 10u);

    if (bx < 7u) {
        unsigned vi = bx * 3200u + t;
        unsigned ri = rt;
        #pragma unroll
        for (int k = 0; k < 5; ++k) {
            const float f0 = sv[ri];
            const float f1 = sv[ri + 1u];
            float4 w;
            w.x = f0;
            w.y = c1 ? f0 : f1;
            w.z = c2 ? f0 : f1;
            w.w = c3 ? f0 : f1;
            __stcs(&ov[vi], w);
            vi += 640u;
            ri += 256u;
        }
        if (bx == 0u) {
            if (t == 0u) o[0] = p[1] * p[5];
            else if (t < pad) o[t] = p[0];   // pad <= 3
        }
    } else {
        // bx == 7: float4 indices [22400, 24999), guarded
        unsigned vi = 22400u + t;
        unsigned ri = rt;
        #pragma unroll
        for (int k = 0; k < 5; ++k) {
            if (vi < 24999u) {
                const float f0 = sv[ri];
                const float f1 = sv[ri + 1u];
                float4 w;
                w.x = f0;
                w.y = c1 ? f0 : f1;
                w.z = c2 ? f0 : f1;
                w.w = c3 ? f0 : f1;
                __stcs(&ov[vi], w);
            }
            vi += 640u;
            ri += 256u;
        }
        // scalar tail: i in [pad + 99996, 99999), all run 9999 = rbase + 1039
        if (t < 3u - pad) {
            o[pad + 99996u + t] = sv[1039];
        }
    }
}

// ---------------------------------------------------------------------------
extern "C" void kernel_launch(void* const* d_in, const int* in_sizes, int n_in,
                              void* d_out, int out_size)
{
    (void)in_sizes; (void)n_in; (void)out_size;
    const float* x  = (const float*)d_in[0];   // [512, 512]
    const float* w2 = (const float*)d_in[1];   // [256, 512]
    const float* b2 = (const float*)d_in[2];   // [256]
    const float* w3 = (const float*)d_in[3];   // [55, 256]
    const float* b3 = (const float*)d_in[4];   // [55]
    float* out = (float*)d_out;                // [512, 99999]

    gemm1_part_kernel<<<dim3(8, 4, 16), 256>>>(x, w2);
    head_kernel<<<64, 256>>>(b2, w3, b3);
    expand_kernel<<<dim3(8, 512), 640>>>(out);
}

// round 7
// speedup vs baseline: 1.1229x; 1.0081x over previous
#include <cuda_runtime.h>

// Scratch: split-K partials [8][512*256] (4 MB) and x3 [512 x 64].
static __device__ float g_part[8][512 * 256];
static __device__ float g_x3[512 * 64];

// ---------------------------------------------------------------------------
// Kernel A1: split-K partial GEMM.  part[z] = x[32r x 64k] @ w2^T[64k x 64h]
// grid (16 rowTiles, 4 hidTiles, 8 kSplits) = 512 blocks, 128 threads.
// Single-wave: 128-thr blocks -> 6/SM cap, 512 blocks all resident at once.
// 4x4 register tiles, 8/16-strided rows/cols, single load phase (K=64).
// ---------------------------------------------------------------------------
__global__ void __launch_bounds__(128) gemm1_part_kernel(
    const float* __restrict__ x,    // [512, 512]
    const float* __restrict__ w2)   // [256, 512]
{
    __shared__ float xs[32][68];
    __shared__ float ws[64][68];

    const int t  = threadIdx.x;
    const int r0 = blockIdx.x * 32;
    const int h0 = blockIdx.y * 64;
    const int k0 = blockIdx.z * 64;

    // load x tile: 32 rows x 64 k = 512 float4 (4 per thread), coalesced
    #pragma unroll
    for (int i = 0; i < 4; ++i) {
        const int idx = t + i * 128;
        const int r   = idx >> 4;          // 0..31
        const int kq  = (idx & 15) * 4;    // 0..60
        float4 v = *reinterpret_cast<const float4*>(
            x + (size_t)(r0 + r) * 512 + k0 + kq);
        *reinterpret_cast<float4*>(&xs[r][kq]) = v;
    }
    // load w2 tile: 64 rows x 64 k = 1024 float4 (8 per thread), coalesced
    #pragma unroll
    for (int i = 0; i < 8; ++i) {
        const int idx = t + i * 128;
        const int r   = idx >> 4;          // 0..63
        const int kq  = (idx & 15) * 4;
        float4 v = *reinterpret_cast<const float4*>(
            w2 + (size_t)(h0 + r) * 512 + k0 + kq);
        *reinterpret_cast<float4*>(&ws[r][kq]) = v;
    }

    float acc[4][4];
    #pragma unroll
    for (int i = 0; i < 4; ++i)
        #pragma unroll
        for (int j = 0; j < 4; ++j) acc[i][j] = 0.f;

    const int tx = t & 15;   // cols tx, tx+16, tx+32, tx+48
    const int ty = t >> 4;   // rows ty, ty+8, ty+16, ty+24

    __syncthreads();

    #pragma unroll
    for (int kq = 0; kq < 64; kq += 4) {
        float4 a[4], bv[4];
        #pragma unroll
        for (int i = 0; i < 4; ++i)
            a[i] = *reinterpret_cast<const float4*>(&xs[ty + 8 * i][kq]);
        #pragma unroll
        for (int j = 0; j < 4; ++j)
            bv[j] = *reinterpret_cast<const float4*>(&ws[tx + 16 * j][kq]);
        #pragma unroll
        for (int i = 0; i < 4; ++i)
            #pragma unroll
            for (int j = 0; j < 4; ++j) {
                acc[i][j] = fmaf(a[i].x, bv[j].x, acc[i][j]);
                acc[i][j] = fmaf(a[i].y, bv[j].y, acc[i][j]);
                acc[i][j] = fmaf(a[i].z, bv[j].z, acc[i][j]);
                acc[i][j] = fmaf(a[i].w, bv[j].w, acc[i][j]);
            }
    }

    float* dst = g_part[blockIdx.z];
    #pragma unroll
    for (int i = 0; i < 4; ++i)
        #pragma unroll
        for (int j = 0; j < 4; ++j)
            dst[(size_t)(r0 + ty + 8 * i) * 256 + h0 + tx + 16 * j] = acc[i][j];
}

// ---------------------------------------------------------------------------
// Kernel A2: reduce 8 partials + bias + LeakyReLU, GEMM2 with w3 staged
// through smem, + softmaxes -> x3.  8 rows/block, 256 threads, grid 64.
// ---------------------------------------------------------------------------
__global__ void __launch_bounds__(256) head_kernel(
    const float* __restrict__ b2,   // [256]
    const float* __restrict__ w3,   // [55, 256]
    const float* __restrict__ b3)   // [55]
{
    __shared__ float hs[8][260];
    __shared__ float ws[55][68];
    __shared__ float zs[8][60];

    const int t  = threadIdx.x;
    const int r0 = blockIdx.x * 8;

    const float bb = b2[t];
    #pragma unroll
    for (int i = 0; i < 8; ++i) {
        const size_t off = (size_t)(r0 + i) * 256 + t;
        float s = bb;
        #pragma unroll
        for (int z = 0; z < 8; ++z) s += g_part[z][off];
        hs[i][t] = (s >= 0.f) ? s : 0.01f * s;
    }

    const int o0 = t;
    const int o1 = t + 256;
    const int r0o = o0 & 7, c0o = o0 >> 3;
    const int r1o = o1 & 7, c1o = o1 >> 3;
    float acc0 = 0.f, acc1 = 0.f;

    #pragma unroll
    for (int chunk = 0; chunk < 4; ++chunk) {
        __syncthreads();
        for (int idx = t; idx < 880; idx += 256) {
            const int c = idx >> 4;
            const int j = (idx & 15) * 4;
            float4 v = *reinterpret_cast<const float4*>(
                w3 + (size_t)c * 256 + chunk * 64 + j);
            *reinterpret_cast<float4*>(&ws[c][j]) = v;
        }
        __syncthreads();

        #pragma unroll 4
        for (int k = 0; k < 16; ++k) {
            const int kj = k * 4;
            {
                const float4 a = *reinterpret_cast<const float4*>(
                    &hs[r0o][chunk * 64 + kj]);
                const float4 w = *reinterpret_cast<const float4*>(&ws[c0o][kj]);
                acc0 = fmaf(a.x, w.x, acc0); acc0 = fmaf(a.y, w.y, acc0);
                acc0 = fmaf(a.z, w.z, acc0); acc0 = fmaf(a.w, w.w, acc0);
            }
            if (o1 < 440) {
                const float4 a = *reinterpret_cast<const float4*>(
                    &hs[r1o][chunk * 64 + kj]);
                const float4 w = *reinterpret_cast<const float4*>(&ws[c1o][kj]);
                acc1 = fmaf(a.x, w.x, acc1); acc1 = fmaf(a.y, w.y, acc1);
                acc1 = fmaf(a.z, w.z, acc1); acc1 = fmaf(a.w, w.w, acc1);
            }
        }
    }
    zs[r0o][c0o] = acc0 + b3[c0o];
    if (o1 < 440) zs[r1o][c1o] = acc1 + b3[c1o];
    __syncthreads();

    if (t < 48) {
        const int r     = t / 6;
        const int g     = t - 6 * r;
        const int start = (g == 0) ? 0 : 5 + 10 * (g - 1);
        const int len   = (g == 0) ? 5 : 10;
        float m = -3.0e38f;
        for (int c = 0; c < len; ++c) m = fmaxf(m, zs[r][start + c]);
        float s = 0.f;
        for (int c = 0; c < len; ++c) s += __expf(zs[r][start + c] - m);
        const float inv = 1.0f / s;
        float* dst = &g_x3[(size_t)(r0 + r) * 64];
        for (int c = 0; c < len; ++c)
            dst[start + c] = __expf(zs[r][start + c] - m) * inv;
    }
}

// ---------------------------------------------------------------------------
// Kernel B: expansion.  out[b, i] constant over runs of 10 (r = i/10).
// grid (8, 512), 640 threads; loop-invariant per-thread run phase;
// streaming (evict-first) float4 stores.
// ---------------------------------------------------------------------------
__global__ void __launch_bounds__(640) expand_kernel(float* __restrict__ out)
{
    __shared__ float p[64];
    __shared__ float sv[1288];

    const unsigned t   = threadIdx.x;
    const unsigned bx  = blockIdx.x;
    const unsigned b   = blockIdx.y;
    const unsigned pad = b & 3u;
    const unsigned rbase = bx * 1280u;   // multiple of 10

    if (t < 64u) p[t] = g_x3[(size_t)b * 64u + t];
    __syncthreads();

    #pragma unroll
    for (unsigned kk = 0; kk < 3u; ++kk) {
        const unsigned ri = t + kk * 640u;
        if (ri < 1282u) {
            const unsigned r = rbase + ri;
            float v = 0.f;
            if (r < 10000u) {
                if (r == 0u) {
                    v = p[0];
                } else if (r < 10u) {
                    v = p[1] * p[5 + r];
                } else if (r < 100u) {
                    const unsigned q1 = r / 10u;
                    v = p[2] * p[5 + q1] * p[15 + (r - 10u * q1)];
                } else if (r < 1000u) {
                    const unsigned q1 = r / 10u, q2 = r / 100u;
                    v = p[3] * p[5 + q2] * p[15 + (q1 - 10u * q2)]
                             * p[25 + (r - 10u * q1)];
                } else {
                    const unsigned q1 = r / 10u, q2 = r / 100u, q3 = r / 1000u;
                    v = p[4] * p[5 + q3] * p[15 + (q2 - 10u * q3)]
                             * p[25 + (q1 - 10u * q2)] * p[35 + (r - 10u * q1)];
                }
            }
            sv[ri] = v;
        }
    }
    __syncthreads();

    float* o = out + (size_t)b * 99999u;
    float4* ov = reinterpret_cast<float4*>(o + pad);   // 16B-aligned

    const unsigned ph  = pad + 4u * t;       // < 2560
    const unsigned rt  = ph / 10u;
    const unsigned rem = ph - 10u * rt;
    const bool c1 = (rem + 1u < 10u);
    const bool c2 = (rem + 2u < 10u);
    const bool c3 = (rem + 3u < 10u);

    if (bx < 7u) {
        unsigned vi = bx * 3200u + t;
        unsigned ri = rt;
        #pragma unroll
        for (int k = 0; k < 5; ++k) {
            const float f0 = sv[ri];
            const float f1 = sv[ri + 1u];
            float4 w;
            w.x = f0;
            w.y = c1 ? f0 : f1;
            w.z = c2 ? f0 : f1;
            w.w = c3 ? f0 : f1;
            __stcs(&ov[vi], w);
            vi += 640u;
            ri += 256u;
        }
        if (bx == 0u) {
            if (t == 0u) o[0] = p[1] * p[5];
            else if (t < pad) o[t] = p[0];   // pad <= 3
        }
    } else {
        unsigned vi = 22400u + t;
        unsigned ri = rt;
        #pragma unroll
        for (int k = 0; k < 5; ++k) {
            if (vi < 24999u) {
                const float f0 = sv[ri];
                const float f1 = sv[ri + 1u];
                float4 w;
                w.x = f0;
                w.y = c1 ? f0 : f1;
                w.z = c2 ? f0 : f1;
                w.w = c3 ? f0 : f1;
                __stcs(&ov[vi], w);
            }
            vi += 640u;
            ri += 256u;
        }
        if (t < 3u - pad) {
            o[pad + 99996u + t] = sv[1039];
        }
    }
}

// ---------------------------------------------------------------------------
extern "C" void kernel_launch(void* const* d_in, const int* in_sizes, int n_in,
                              void* d_out, int out_size)
{
    (void)in_sizes; (void)n_in; (void)out_size;
    const float* x  = (const float*)d_in[0];   // [512, 512]
    const float* w2 = (const float*)d_in[1];   // [256, 512]
    const float* b2 = (const float*)d_in[2];   // [256]
    const float* w3 = (const float*)d_in[3];   // [55, 256]
    const float* b3 = (const float*)d_in[4];   // [55]
    float* out = (float*)d_out;                // [512, 99999]

    gemm1_part_kernel<<<dim3(16, 4, 8), 128>>>(x, w2);
    head_kernel<<<64, 256>>>(b2, w3, b3);
    expand_kernel<<<dim3(8, 512), 640>>>(out);
}